// round 6
// baseline (speedup 1.0000x reference)
#include <cuda_runtime.h>
#include <math.h>

// ---------------- problem constants ----------------
constexpr int B  = 128;
constexpr int C  = 256;
constexpr int HW = 1024;          // 32*32
constexpr int N  = 2048;          // 2*HW tokens per batch
constexpr int D  = 64;
constexpr int S  = 8;
constexpr int MH = 128;
constexpr int NC = 15;
constexpr float LN_EPS = 1e-5f;
constexpr float SA_EPS = 1e-8f;

// ---------------- device scratch (static, allocation-free) ----------------
// token features, k, v stored d-major: [b][d][n]  (n contiguous -> coalesced)
__device__ float g_tok[(size_t)B * D * N];     // 64 MB
__device__ float g_k  [(size_t)B * D * N];     // 64 MB
__device__ float g_v  [(size_t)B * D * N];     // 64 MB
__device__ float g_slots[B * S * D];
__device__ float g_q    [B * S * D];
__device__ float g_attn [(size_t)B * N * S];   // 8 MB, [b][n][s]
__device__ float g_colsum[B * S];
__device__ float g_upd  [B * S * D];

// =====================================================================
// K1: 1x1 conv (GEMM 64x256 @ 256x128-tile) + bias + LN(norm) + LN(ni)
// grid: B*2*8 = 2048 CTAs, 256 threads. CTA = 128 tokens of one image/conv.
// output: g_tok[b][d][n]
// =====================================================================
__global__ __launch_bounds__(256) void k_conv_ln(
    const float* __restrict__ x1, const float* __restrict__ x2,
    const float* __restrict__ cw1, const float* __restrict__ cb1,
    const float* __restrict__ cw2, const float* __restrict__ cb2,
    const float* __restrict__ nw,  const float* __restrict__ nb,
    const float* __restrict__ niw, const float* __restrict__ nib)
{
    __shared__ float xs[32][128];
    __shared__ float ws[32][68];
    __shared__ float s_m1[128], s_q1[128], s_m2[128], s_q2[128];
    __shared__ float p_nw[64], p_nb[64], p_iw[64], p_ib[64];

    const int t    = threadIdx.x;
    const int cid  = blockIdx.x;
    const int b    = cid >> 4;
    const int r    = cid & 15;
    const int conv = r >> 3;
    const int tile = r & 7;
    const int hw0  = tile * 128;

    const float* x    = (conv ? x2 : x1) + (size_t)b * C * HW + hw0;
    const float* w    = conv ? cw2 : cw1;
    const float* bias = conv ? cb2 : cb1;

    if (t < 64)  { p_nw[t] = nw[t]; p_nb[t] = nb[t]; p_iw[t] = niw[t]; p_ib[t] = nib[t]; }
    if (t < 128) { s_m1[t] = 0.f; s_q1[t] = 0.f; s_m2[t] = 0.f; s_q2[t] = 0.f; }

    const int dgrp = t >> 5, lane = t & 31;
    const int d0 = dgrp * 8, tk0 = lane * 4;

    float acc[8][4];
#pragma unroll
    for (int j = 0; j < 8; j++)
#pragma unroll
        for (int i = 0; i < 4; i++) acc[j][i] = 0.f;

    for (int c0 = 0; c0 < C; c0 += 32) {
        __syncthreads();
#pragma unroll
        for (int j = 0; j < 16; j++) {
            int e = t + 256 * j;
            xs[e >> 7][e & 127] = x[(size_t)(c0 + (e >> 7)) * HW + (e & 127)];
        }
#pragma unroll
        for (int j = 0; j < 8; j++) {
            int e = t + 256 * j;
            ws[e & 31][e >> 5] = w[(e >> 5) * C + c0 + (e & 31)];
        }
        __syncthreads();
#pragma unroll
        for (int cc = 0; cc < 32; cc++) {
            float4 xv = *(const float4*)&xs[cc][tk0];
            float4 wa = *(const float4*)&ws[cc][d0];
            float4 wb = *(const float4*)&ws[cc][d0 + 4];
            float wr[8] = {wa.x, wa.y, wa.z, wa.w, wb.x, wb.y, wb.z, wb.w};
#pragma unroll
            for (int j = 0; j < 8; j++) {
                acc[j][0] = fmaf(wr[j], xv.x, acc[j][0]);
                acc[j][1] = fmaf(wr[j], xv.y, acc[j][1]);
                acc[j][2] = fmaf(wr[j], xv.z, acc[j][2]);
                acc[j][3] = fmaf(wr[j], xv.w, acc[j][3]);
            }
        }
    }

    // bias
#pragma unroll
    for (int j = 0; j < 8; j++) {
        float bb = __ldg(&bias[d0 + j]);
#pragma unroll
        for (int i = 0; i < 4; i++) acc[j][i] += bb;
    }
    __syncthreads();
    // LN1 stats
#pragma unroll
    for (int i = 0; i < 4; i++) {
        float ps = 0.f, pq = 0.f;
#pragma unroll
        for (int j = 0; j < 8; j++) { ps += acc[j][i]; pq += acc[j][i] * acc[j][i]; }
        atomicAdd(&s_m1[tk0 + i], ps);
        atomicAdd(&s_q1[tk0 + i], pq);
    }
    __syncthreads();
    // apply LN1, accumulate LN2 stats
#pragma unroll
    for (int i = 0; i < 4; i++) {
        float mu = s_m1[tk0 + i] * (1.f / 64.f);
        float var = s_q1[tk0 + i] * (1.f / 64.f) - mu * mu;
        float rs = rsqrtf(var + LN_EPS);
        float ps = 0.f, pq = 0.f;
#pragma unroll
        for (int j = 0; j < 8; j++) {
            float v = (acc[j][i] - mu) * rs * p_nw[d0 + j] + p_nb[d0 + j];
            acc[j][i] = v;
            ps += v; pq += v * v;
        }
        atomicAdd(&s_m2[tk0 + i], ps);
        atomicAdd(&s_q2[tk0 + i], pq);
    }
    __syncthreads();
    float mu2[4], rs2[4];
#pragma unroll
    for (int i = 0; i < 4; i++) {
        float m = s_m2[tk0 + i] * (1.f / 64.f);
        float v = s_q2[tk0 + i] * (1.f / 64.f) - m * m;
        mu2[i] = m; rs2[i] = rsqrtf(v + LN_EPS);
    }
    const int n0 = conv * HW + hw0;
    float* outp = g_tok + (size_t)b * D * N + n0;
#pragma unroll
    for (int j = 0; j < 8; j++) {
        float ww = p_iw[d0 + j], bb = p_ib[d0 + j];
        float4 o;
        o.x = (acc[j][0] - mu2[0]) * rs2[0] * ww + bb;
        o.y = (acc[j][1] - mu2[1]) * rs2[1] * ww + bb;
        o.z = (acc[j][2] - mu2[2]) * rs2[2] * ww + bb;
        o.w = (acc[j][3] - mu2[3]) * rs2[3] * ww + bb;
        *(float4*)&outp[(size_t)(d0 + j) * N + tk0] = o;
    }
}

// =====================================================================
// K2: k = tok @ Wk^T, v = tok @ Wv^T.  grid 2048, 256 threads.
// =====================================================================
__global__ __launch_bounds__(256) void k_kv(
    const float* __restrict__ Wk, const float* __restrict__ Wv)
{
    __shared__ float ts[32][128];
    __shared__ float wks[32][68], wvs[32][68];

    const int t = threadIdx.x;
    const int b = blockIdx.x >> 4;
    const int n0 = (blockIdx.x & 15) * 128;
    const int dgrp = t >> 5, lane = t & 31;
    const int d0 = dgrp * 8, tk0 = lane * 4;

    float ka[8][4], va[8][4];
#pragma unroll
    for (int j = 0; j < 8; j++)
#pragma unroll
        for (int i = 0; i < 4; i++) { ka[j][i] = 0.f; va[j][i] = 0.f; }

    const float* tokb = g_tok + (size_t)b * D * N + n0;

    for (int c0 = 0; c0 < D; c0 += 32) {
        __syncthreads();
#pragma unroll
        for (int j = 0; j < 16; j++) {
            int e = t + 256 * j;
            ts[e >> 7][e & 127] = tokb[(size_t)(c0 + (e >> 7)) * N + (e & 127)];
        }
#pragma unroll
        for (int j = 0; j < 8; j++) {
            int e = t + 256 * j;
            int d = e >> 5, cc = e & 31;
            wks[cc][d] = Wk[d * D + c0 + cc];
            wvs[cc][d] = Wv[d * D + c0 + cc];
        }
        __syncthreads();
#pragma unroll
        for (int cc = 0; cc < 32; cc++) {
            float4 xv = *(const float4*)&ts[cc][tk0];
            float4 ka4 = *(const float4*)&wks[cc][d0];
            float4 kb4 = *(const float4*)&wks[cc][d0 + 4];
            float4 va4 = *(const float4*)&wvs[cc][d0];
            float4 vb4 = *(const float4*)&wvs[cc][d0 + 4];
            float kr[8] = {ka4.x, ka4.y, ka4.z, ka4.w, kb4.x, kb4.y, kb4.z, kb4.w};
            float vr[8] = {va4.x, va4.y, va4.z, va4.w, vb4.x, vb4.y, vb4.z, vb4.w};
#pragma unroll
            for (int j = 0; j < 8; j++) {
                ka[j][0] = fmaf(kr[j], xv.x, ka[j][0]);
                ka[j][1] = fmaf(kr[j], xv.y, ka[j][1]);
                ka[j][2] = fmaf(kr[j], xv.z, ka[j][2]);
                ka[j][3] = fmaf(kr[j], xv.w, ka[j][3]);
                va[j][0] = fmaf(vr[j], xv.x, va[j][0]);
                va[j][1] = fmaf(vr[j], xv.y, va[j][1]);
                va[j][2] = fmaf(vr[j], xv.z, va[j][2]);
                va[j][3] = fmaf(vr[j], xv.w, va[j][3]);
            }
        }
    }
    float* kp = g_k + (size_t)b * D * N + n0;
    float* vp = g_v + (size_t)b * D * N + n0;
#pragma unroll
    for (int j = 0; j < 8; j++) {
        float4 ok = {ka[j][0], ka[j][1], ka[j][2], ka[j][3]};
        float4 ov = {va[j][0], va[j][1], va[j][2], va[j][3]};
        *(float4*)&kp[(size_t)(d0 + j) * N + tk0] = ok;
        *(float4*)&vp[(size_t)(d0 + j) * N + tk0] = ov;
    }
}

// =====================================================================
// K3: slots init  slots = mu + exp(log_sigma)*noise
// =====================================================================
__global__ void k_init_slots(const float* __restrict__ mu,
                             const float* __restrict__ ls,
                             const float* __restrict__ noise)
{
    int i = blockIdx.x * 256 + threadIdx.x;   // grid 256 -> 65536
    int d = i & 63;
    g_slots[i] = mu[d] + expf(ls[d]) * noise[i];
}

// =====================================================================
// K4: sn = LN(slots, ns), q = sn @ Wq^T * D^-0.5; also zeroes colsum.
// grid B, 256 threads (warp w = slot w).
// =====================================================================
__global__ __launch_bounds__(256) void k_q(
    const float* __restrict__ Wq,
    const float* __restrict__ nsw, const float* __restrict__ nsb)
{
    __shared__ float wq[64][65];
    __shared__ float sn[8][64];
    const int t = threadIdx.x, b = blockIdx.x;
    const int w = t >> 5, lane = t & 31;

    if (t < 8) g_colsum[b * 8 + t] = 0.f;
#pragma unroll
    for (int j = 0; j < 16; j++) {
        int e = t + 256 * j;
        wq[e >> 6][e & 63] = Wq[e];
    }
    float v0 = g_slots[b * 512 + w * 64 + lane];
    float v1 = g_slots[b * 512 + w * 64 + lane + 32];
    float s = v0 + v1, q2 = v0 * v0 + v1 * v1;
#pragma unroll
    for (int o = 16; o > 0; o >>= 1) {
        s  += __shfl_xor_sync(~0u, s, o);
        q2 += __shfl_xor_sync(~0u, q2, o);
    }
    float mu = s * (1.f / 64.f);
    float rs = rsqrtf(q2 * (1.f / 64.f) - mu * mu + LN_EPS);
    sn[w][lane]      = (v0 - mu) * rs * __ldg(&nsw[lane])      + __ldg(&nsb[lane]);
    sn[w][lane + 32] = (v1 - mu) * rs * __ldg(&nsw[lane + 32]) + __ldg(&nsb[lane + 32]);
    __syncthreads();

    float a0 = 0.f, a1 = 0.f;
#pragma unroll
    for (int din = 0; din < 64; din++) {
        float sv = sn[w][din];
        a0 = fmaf(sv, wq[lane][din], a0);
        a1 = fmaf(sv, wq[lane + 32][din], a1);
    }
    const float scale = 0.125f;   // D^-0.5
    g_q[b * 512 + w * 64 + lane]      = a0 * scale;
    g_q[b * 512 + w * 64 + lane + 32] = a1 * scale;
}

// =====================================================================
// K5a: logits = k.q, softmax over S, +eps, store attn, accumulate colsum.
// grid B*8 (256 tokens per CTA), 256 threads (1 token each).
// =====================================================================
__global__ __launch_bounds__(256) void k_attn(void)
{
    __shared__ float qs[512];
    __shared__ float scs[8];
    const int t = threadIdx.x;
    const int b = blockIdx.x >> 3;
    const int n0 = (blockIdx.x & 7) * 256;

    if (t < 8) scs[t] = 0.f;
    qs[t] = g_q[b * 512 + t];
    qs[t + 256] = g_q[b * 512 + t + 256];
    __syncthreads();

    const float* kb = g_k + (size_t)b * D * N + n0 + t;
    float lg[8];
#pragma unroll
    for (int s = 0; s < 8; s++) lg[s] = 0.f;
#pragma unroll 8
    for (int d = 0; d < 64; d++) {
        float kv = kb[(size_t)d * N];
#pragma unroll
        for (int s = 0; s < 8; s++) lg[s] = fmaf(kv, qs[s * 64 + d], lg[s]);
    }
    float m = lg[0];
#pragma unroll
    for (int s = 1; s < 8; s++) m = fmaxf(m, lg[s]);
    float sum = 0.f;
#pragma unroll
    for (int s = 0; s < 8; s++) { lg[s] = expf(lg[s] - m); sum += lg[s]; }
    float inv = 1.f / sum;
#pragma unroll
    for (int s = 0; s < 8; s++) lg[s] = lg[s] * inv + SA_EPS;

    float* ap = g_attn + ((size_t)(b * N + n0 + t)) * 8;
    float4 o1 = {lg[0], lg[1], lg[2], lg[3]};
    float4 o2 = {lg[4], lg[5], lg[6], lg[7]};
    *(float4*)ap = o1;
    *(float4*)(ap + 4) = o2;

#pragma unroll
    for (int s = 0; s < 8; s++) {
        float v = lg[s];
#pragma unroll
        for (int o = 16; o > 0; o >>= 1) v += __shfl_xor_sync(~0u, v, o);
        if ((t & 31) == 0) atomicAdd(&scs[s], v);
    }
    __syncthreads();
    if (t < 8) atomicAdd(&g_colsum[b * 8 + t], scs[t]);
}

// =====================================================================
// K5b: updates[s][d] = (sum_n attn[n][s] * v[d][n]) / colsum[s]
// grid B, 256 threads. warp w owns d = w*8 .. w*8+7.
// =====================================================================
__global__ __launch_bounds__(256) void k_updates(void)
{
    __shared__ float as[256][9];
    const int t = threadIdx.x, b = blockIdx.x;
    const int w = t >> 5, lane = t & 31;

    float acc[8][8];
#pragma unroll
    for (int j = 0; j < 8; j++)
#pragma unroll
        for (int s = 0; s < 8; s++) acc[j][s] = 0.f;

    const float* vb = g_v + (size_t)b * D * N;
    const float* ab = g_attn + (size_t)b * N * 8;

    for (int ch = 0; ch < 8; ch++) {
        const int n0 = ch * 256;
        __syncthreads();
        {
            float4 a1 = *(const float4*)&ab[(size_t)(n0 + t) * 8];
            float4 a2 = *(const float4*)&ab[(size_t)(n0 + t) * 8 + 4];
            as[t][0] = a1.x; as[t][1] = a1.y; as[t][2] = a1.z; as[t][3] = a1.w;
            as[t][4] = a2.x; as[t][5] = a2.y; as[t][6] = a2.z; as[t][7] = a2.w;
        }
        __syncthreads();
#pragma unroll
        for (int it = 0; it < 8; it++) {
            int n = n0 + it * 32 + lane;
            float ar[8];
#pragma unroll
            for (int s = 0; s < 8; s++) ar[s] = as[it * 32 + lane][s];
#pragma unroll
            for (int j = 0; j < 8; j++) {
                float vv = vb[(size_t)(w * 8 + j) * N + n];
#pragma unroll
                for (int s = 0; s < 8; s++) acc[j][s] = fmaf(vv, ar[s], acc[j][s]);
            }
        }
    }
#pragma unroll
    for (int j = 0; j < 8; j++) {
#pragma unroll
        for (int s = 0; s < 8; s++) {
            float v = acc[j][s];
#pragma unroll
            for (int o = 16; o > 0; o >>= 1) v += __shfl_xor_sync(~0u, v, o);
            if (lane == s) {
                float cs = __ldg(&g_colsum[b * 8 + s]);
                g_upd[b * 512 + s * 64 + w * 8 + j] = v / cs;
            }
        }
    }
}

// =====================================================================
// K6: GRU cell + residual MLP -> new slots.  grid B, 256 threads.
// =====================================================================
__global__ __launch_bounds__(256) void k_gru_mlp(
    const float* __restrict__ wih, const float* __restrict__ whh,
    const float* __restrict__ bih, const float* __restrict__ bhh,
    const float* __restrict__ nmw, const float* __restrict__ nmb,
    const float* __restrict__ mw1, const float* __restrict__ mb1,
    const float* __restrict__ mw2, const float* __restrict__ mb2)
{
    __shared__ float us[8][64], sp[8][64];
    __shared__ float gih[8][192], ghh[8][192];
    __shared__ float ws1[32][65], ws2[32][65];
    __shared__ float lns[8][64];
    __shared__ float h1s[8][128];

    const int t = threadIdx.x, b = blockIdx.x;
    const int w = t >> 5, lane = t & 31;

    ((float*)us)[t]       = g_upd[b * 512 + t];
    ((float*)us)[t + 256] = g_upd[b * 512 + t + 256];
    ((float*)sp)[t]       = g_slots[b * 512 + t];
    ((float*)sp)[t + 256] = g_slots[b * 512 + t + 256];

    // gi / gh : 6 chunks of 32 outputs
    for (int c = 0; c < 6; c++) {
        const int o0 = c * 32;
        __syncthreads();
#pragma unroll
        for (int j = 0; j < 8; j++) {
            int e = t + 256 * j;
            int oo = e >> 6, din = e & 63;
            ws1[oo][din] = wih[(o0 + oo) * 64 + din];
            ws2[oo][din] = whh[(o0 + oo) * 64 + din];
        }
        __syncthreads();
        float a = __ldg(&bih[o0 + lane]);
        float h = __ldg(&bhh[o0 + lane]);
#pragma unroll
        for (int din = 0; din < 64; din++) {
            a = fmaf(us[w][din], ws1[lane][din], a);
            h = fmaf(sp[w][din], ws2[lane][din], h);
        }
        gih[w][o0 + lane] = a;
        ghh[w][o0 + lane] = h;
    }
    __syncthreads();

    // gates (torch order r,z,n)
    float sn0, sn1;
    {
        int dd = lane;
        float r = 1.f / (1.f + expf(-(gih[w][dd] + ghh[w][dd])));
        float z = 1.f / (1.f + expf(-(gih[w][64 + dd] + ghh[w][64 + dd])));
        float nn = tanhf(gih[w][128 + dd] + r * ghh[w][128 + dd]);
        sn0 = (1.f - z) * nn + z * sp[w][dd];
    }
    {
        int dd = lane + 32;
        float r = 1.f / (1.f + expf(-(gih[w][dd] + ghh[w][dd])));
        float z = 1.f / (1.f + expf(-(gih[w][64 + dd] + ghh[w][64 + dd])));
        float nn = tanhf(gih[w][128 + dd] + r * ghh[w][128 + dd]);
        sn1 = (1.f - z) * nn + z * sp[w][dd];
    }
    // LN(nm) of new slots
    float s = sn0 + sn1, q2 = sn0 * sn0 + sn1 * sn1;
#pragma unroll
    for (int o = 16; o > 0; o >>= 1) {
        s  += __shfl_xor_sync(~0u, s, o);
        q2 += __shfl_xor_sync(~0u, q2, o);
    }
    float mu = s * (1.f / 64.f);
    float rs = rsqrtf(q2 * (1.f / 64.f) - mu * mu + LN_EPS);
    lns[w][lane]      = (sn0 - mu) * rs * __ldg(&nmw[lane])      + __ldg(&nmb[lane]);
    lns[w][lane + 32] = (sn1 - mu) * rs * __ldg(&nmw[lane + 32]) + __ldg(&nmb[lane + 32]);
    __syncthreads();

    // MLP layer 1: 4 chunks of 32 hidden units
    for (int c = 0; c < 4; c++) {
        const int m0 = c * 32;
        __syncthreads();
#pragma unroll
        for (int j = 0; j < 8; j++) {
            int e = t + 256 * j;
            int mm = e >> 6, din = e & 63;
            ws1[mm][din] = mw1[(m0 + mm) * 64 + din];
        }
        __syncthreads();
        float a = __ldg(&mb1[m0 + lane]);
#pragma unroll
        for (int din = 0; din < 64; din++)
            a = fmaf(lns[w][din], ws1[lane][din], a);
        h1s[w][m0 + lane] = fmaxf(a, 0.f);
    }
    __syncthreads();

    // MLP layer 2: accumulate over 4 chunks of 32 hidden units
    float out0 = __ldg(&mb2[lane]);
    float out1 = __ldg(&mb2[lane + 32]);
    for (int c = 0; c < 4; c++) {
        const int m0 = c * 32;
        __syncthreads();
#pragma unroll
        for (int j = 0; j < 8; j++) {
            int e = t + 256 * j;               // d = e>>5 (0..63), mm = e&31
            ws1[e & 31][e >> 5] = mw2[(e >> 5) * 128 + m0 + (e & 31)];
        }
        __syncthreads();
#pragma unroll
        for (int mm = 0; mm < 32; mm++) {
            float hv = h1s[w][m0 + mm];
            out0 = fmaf(hv, ws1[mm][lane], out0);
            out1 = fmaf(hv, ws1[mm][lane + 32], out1);
        }
    }
    g_slots[b * 512 + w * 64 + lane]      = sn0 + out0;
    g_slots[b * 512 + w * 64 + lane + 32] = sn1 + out1;
}

// =====================================================================
// K7: fused = mean(slots, axis=S); out = fused @ head_w^T + head_b
// grid B, 64 threads.
// =====================================================================
__global__ void k_head(const float* __restrict__ hw_, const float* __restrict__ hb_,
                       float* __restrict__ out)
{
    __shared__ float f[64];
    const int t = threadIdx.x, b = blockIdx.x;
    float s = 0.f;
#pragma unroll
    for (int ss = 0; ss < 8; ss++) s += g_slots[b * 512 + ss * 64 + t];
    f[t] = s * (1.f / 8.f);
    __syncthreads();
    if (t < NC) {
        float a = hb_[t];
#pragma unroll
        for (int d = 0; d < 64; d++) a = fmaf(f[d], hw_[t * 64 + d], a);
        out[b * NC + t] = a;
    }
}

// =====================================================================
extern "C" void kernel_launch(void* const* d_in, const int* in_sizes, int n_in,
                              void* d_out, int out_size)
{
    const float* x1   = (const float*)d_in[0];
    const float* x2   = (const float*)d_in[1];
    const float* c1w  = (const float*)d_in[2];
    const float* c1b  = (const float*)d_in[3];
    const float* c2w  = (const float*)d_in[4];
    const float* c2b  = (const float*)d_in[5];
    const float* nw   = (const float*)d_in[6];
    const float* nb   = (const float*)d_in[7];
    const float* niw  = (const float*)d_in[8];
    const float* nib  = (const float*)d_in[9];
    const float* nsw  = (const float*)d_in[10];
    const float* nsb  = (const float*)d_in[11];
    const float* nmw  = (const float*)d_in[12];
    const float* nmb  = (const float*)d_in[13];
    const float* smu  = (const float*)d_in[14];
    const float* sls  = (const float*)d_in[15];
    const float* Wq   = (const float*)d_in[16];
    const float* Wk   = (const float*)d_in[17];
    const float* Wv   = (const float*)d_in[18];
    const float* wih  = (const float*)d_in[19];
    const float* whh  = (const float*)d_in[20];
    const float* bih  = (const float*)d_in[21];
    const float* bhh  = (const float*)d_in[22];
    const float* mw1  = (const float*)d_in[23];
    const float* mb1  = (const float*)d_in[24];
    const float* mw2  = (const float*)d_in[25];
    const float* mb2  = (const float*)d_in[26];
    const float* hw_  = (const float*)d_in[27];
    const float* hb_  = (const float*)d_in[28];
    const float* noise= (const float*)d_in[29];
    float* out = (float*)d_out;

    k_conv_ln<<<B * 16, 256>>>(x1, x2, c1w, c1b, c2w, c2b, nw, nb, niw, nib);
    k_kv<<<B * 16, 256>>>(Wk, Wv);
    k_init_slots<<<256, 256>>>(smu, sls, noise);

    for (int it = 0; it < 3; it++) {
        k_q<<<B, 256>>>(Wq, nsw, nsb);
        k_attn<<<B * 8, 256>>>();
        k_updates<<<B, 256>>>();
        k_gru_mlp<<<B, 256>>>(wih, whh, bih, bhh, nmw, nmb, mw1, mb1, mw2, mb2);
    }
    k_head<<<B, 64>>>(hw_, hb_, out);
}